// round 3
// baseline (speedup 1.0000x reference)
#include <cuda_runtime.h>
#include <math.h>
#include <stdint.h>

#define N_DST 20000
#define N_SRC 100000
#define KNB 16
#define NE (N_DST * KNB)   // 320000 edges
#define D_NODE 128
#define D_TIME 128
#define D_EDGE 128
#define D_Q 256
#define D_K 384

// ---------------- static device scratch (no allocations allowed) ----------------
__device__ float g_C[(size_t)NE * 256];        // [edge_feat | te] per edge
__device__ float g_KV[(size_t)NE * 512];       // kproj(0:256) | vproj(256:512)
__device__ float g_NodeP[(size_t)N_SRC * 512]; // node_emb @ [Wk_node;Wv_node]^T + [bk;bv]
__device__ float g_Bkv_node[128 * 512];
__device__ float g_Bkv_et[256 * 512];
__device__ float g_bkv[512];
__device__ float g_Bq[256 * 256];
__device__ float g_Bo[256 * 256];
__device__ float g_B1[384 * 128];
__device__ float g_B2[128 * 128];
__device__ float g_query[(size_t)N_DST * 256];
__device__ float g_Qm[(size_t)N_DST * 256];
__device__ float g_ctx[(size_t)N_DST * 256];
__device__ float g_Hb[(size_t)N_DST * 256];
__device__ float g_X[(size_t)N_DST * 384];
__device__ float g_H1[(size_t)N_DST * 128];
__device__ float g_att[NE];
__device__ float g_part[320];
__device__ float g_attsum;

// ---------------- weight prep ----------------
__global__ void build_Bkv_node_kernel(const float* __restrict__ Wk, const float* __restrict__ Wv,
                                      const float* __restrict__ bk, const float* __restrict__ bv,
                                      float* __restrict__ B, float* __restrict__ bkv) {
    int idx = blockIdx.x * blockDim.x + threadIdx.x;
    if (idx < 128 * 512) {
        int j = idx >> 9, o = idx & 511;
        B[idx] = (o < 256) ? Wk[o * 384 + j] : Wv[(o - 256) * 384 + j];
    }
    if (idx < 512) bkv[idx] = (idx < 256) ? bk[idx] : bv[idx - 256];
}

__global__ void build_Bkv_et_kernel(const float* __restrict__ Wk, const float* __restrict__ Wv,
                                    float* __restrict__ B) {
    int idx = blockIdx.x * blockDim.x + threadIdx.x;
    if (idx < 256 * 512) {
        int j = idx >> 9, o = idx & 511;
        int col = 128 + j;
        B[idx] = (o < 256) ? Wk[o * 384 + col] : Wv[(o - 256) * 384 + col];
    }
}

// generic transpose: W is [O,I] (torch layout), out Bm is [I,O]
__global__ void transpose_kernel(const float* __restrict__ W, float* __restrict__ Bm,
                                 int O, int I) {
    int idx = blockIdx.x * blockDim.x + threadIdx.x;
    if (idx < O * I) {
        int j = idx / O, o = idx % O;
        Bm[idx] = W[o * I + j];
    }
}

// ---------------- elementwise builders ----------------
__global__ void fill_attn_kernel(float* __restrict__ attn_map) {
    int i = blockIdx.x * blockDim.x + threadIdx.x;
    if (i < NE) attn_map[i] = -1.0f;
}

__global__ void build_query_kernel(const float* __restrict__ dst_emb,
                                   const float* __restrict__ b_t,
                                   float* __restrict__ q) {
    int idx = blockIdx.x * blockDim.x + threadIdx.x;
    if (idx < N_DST * 256) {
        int n = idx >> 8, j = idx & 255;
        q[idx] = (j < 128) ? dst_emb[n * 128 + j] : cosf(b_t[j - 128]);
    }
}

__global__ void build_C_kernel(const float* __restrict__ edge_feat,
                               const float* __restrict__ timestamps,
                               const float* __restrict__ last_update,
                               const int* __restrict__ src_idx,
                               const float* __restrict__ w_t,
                               const float* __restrict__ b_t,
                               float* __restrict__ C) {
    size_t idx = (size_t)blockIdx.x * blockDim.x + threadIdx.x;
    if (idx < (size_t)NE * 256) {
        int e = (int)(idx >> 8);
        int j = (int)(idx & 255);
        float v;
        if (j < 128) {
            v = edge_feat[(size_t)e * 128 + j];
        } else {
            int j2 = j - 128;
            float dt = timestamps[e] - last_update[src_idx[e]];
            v = cosf(fmaf(dt, w_t[j2], b_t[j2]));
        }
        C[idx] = v;
    }
}

__global__ void build_X_kernel(const float* __restrict__ dst_emb,
                               const float* __restrict__ Hb,
                               float* __restrict__ X) {
    size_t idx = (size_t)blockIdx.x * blockDim.x + threadIdx.x;
    if (idx < (size_t)N_DST * 384) {
        int n = (int)(idx / 384);
        int j = (int)(idx % 384);
        X[idx] = (j < 128) ? dst_emb[n * 128 + j] : Hb[(size_t)n * 256 + (j - 128)];
    }
}

// ---------------- SGEMM: C[M,N] = A[M,K] @ B[K,N] (+bias)(+gather-add)(+relu) --------
// 128x128 block, BK=8, 256 threads, 8x8 per-thread tile
__global__ __launch_bounds__(256) void sgemm_kernel(
    const float* __restrict__ A, const float* __restrict__ B,
    const float* __restrict__ bias, float* __restrict__ C,
    int M, int N, int K, int relu,
    const float* __restrict__ gtab, const int* __restrict__ gidx) {
    __shared__ float As[8][128];
    __shared__ float Bs[8][128];
    const int tid = threadIdx.x;
    const int brow = blockIdx.y * 128;
    const int bcol = blockIdx.x * 128;
    const int tx = tid & 15;
    const int ty = tid >> 4;
    float acc[8][8];
#pragma unroll
    for (int i = 0; i < 8; i++)
#pragma unroll
        for (int j = 0; j < 8; j++) acc[i][j] = 0.f;

    const int a_row = tid >> 1;
    const int a_col = (tid & 1) * 4;
    const int b_row = tid >> 5;
    const int b_col = (tid & 31) * 4;
    const float* Ab = A + (size_t)brow * K;
    const float* Bb = B + bcol;
    const bool a_ok = (brow + a_row) < M;

    for (int k0 = 0; k0 < K; k0 += 8) {
        float4 av = make_float4(0.f, 0.f, 0.f, 0.f);
        if (a_ok) av = *reinterpret_cast<const float4*>(Ab + (size_t)a_row * K + k0 + a_col);
        float4 bv = *reinterpret_cast<const float4*>(Bb + (size_t)(k0 + b_row) * N + b_col);
        As[a_col + 0][a_row] = av.x;
        As[a_col + 1][a_row] = av.y;
        As[a_col + 2][a_row] = av.z;
        As[a_col + 3][a_row] = av.w;
        *reinterpret_cast<float4*>(&Bs[b_row][b_col]) = bv;
        __syncthreads();
#pragma unroll
        for (int kk = 0; kk < 8; kk++) {
            float4 a0 = *reinterpret_cast<const float4*>(&As[kk][ty * 4]);
            float4 a1 = *reinterpret_cast<const float4*>(&As[kk][64 + ty * 4]);
            float4 b0 = *reinterpret_cast<const float4*>(&Bs[kk][tx * 4]);
            float4 b1 = *reinterpret_cast<const float4*>(&Bs[kk][64 + tx * 4]);
            float af[8] = {a0.x, a0.y, a0.z, a0.w, a1.x, a1.y, a1.z, a1.w};
            float bf[8] = {b0.x, b0.y, b0.z, b0.w, b1.x, b1.y, b1.z, b1.w};
#pragma unroll
            for (int i = 0; i < 8; i++)
#pragma unroll
                for (int j = 0; j < 8; j++) acc[i][j] = fmaf(af[i], bf[j], acc[i][j]);
        }
        __syncthreads();
    }
#pragma unroll
    for (int i = 0; i < 8; i++) {
        int r = brow + ((i < 4) ? (ty * 4 + i) : (64 + ty * 4 + i - 4));
        if (r >= M) continue;
        const float* grow = gtab ? (gtab + (size_t)gidx[r] * N) : nullptr;
#pragma unroll
        for (int jj = 0; jj < 2; jj++) {
            int c = bcol + ((jj == 0) ? tx * 4 : 64 + tx * 4);
            float4 v;
            v.x = acc[i][jj * 4 + 0];
            v.y = acc[i][jj * 4 + 1];
            v.z = acc[i][jj * 4 + 2];
            v.w = acc[i][jj * 4 + 3];
            if (bias) {
                v.x += bias[c]; v.y += bias[c + 1]; v.z += bias[c + 2]; v.w += bias[c + 3];
            }
            if (grow) {
                float4 g = *reinterpret_cast<const float4*>(grow + c);
                v.x += g.x; v.y += g.y; v.z += g.z; v.w += g.w;
            }
            if (relu) {
                v.x = fmaxf(v.x, 0.f); v.y = fmaxf(v.y, 0.f);
                v.z = fmaxf(v.z, 0.f); v.w = fmaxf(v.w, 0.f);
            }
            *reinterpret_cast<float4*>(C + (size_t)r * N + c) = v;
        }
    }
}

// ---------------- attention: one block (128 thr) per destination node ----------------
__global__ void attn_kernel(const float* __restrict__ Q, const float* __restrict__ KV,
                            float* __restrict__ ctx_out, float* __restrict__ att_out) {
    int n = blockIdx.x;
    int t = threadIdx.x;  // 0..127
    __shared__ float q[256];
    __shared__ float sc[2][16];
    __shared__ float p[2][16];
    const float scale = 0.08838834764831845f;  // 1/sqrt(128)
    q[t] = Q[(size_t)n * 256 + t] * scale;
    q[t + 128] = Q[(size_t)n * 256 + 128 + t] * scale;
    __syncthreads();
    int warp = t >> 5, lane = t & 31;
    for (int pair = warp; pair < 32; pair += 4) {
        int h = pair >> 4, k = pair & 15;
        const float* kr = KV + ((size_t)n * KNB + k) * 512 + h * 128;
        float s = 0.f;
#pragma unroll
        for (int j = 0; j < 4; j++) s = fmaf(q[h * 128 + lane + 32 * j], kr[lane + 32 * j], s);
#pragma unroll
        for (int off = 16; off; off >>= 1) s += __shfl_xor_sync(0xffffffffu, s, off);
        if (lane == 0) sc[h][k] = s;
    }
    __syncthreads();
    if (t < 2) {
        float m = -1e30f;
#pragma unroll
        for (int k = 0; k < 16; k++) m = fmaxf(m, sc[t][k]);
        float s = 0.f;
#pragma unroll
        for (int k = 0; k < 16; k++) {
            float e = expf(sc[t][k] - m);
            p[t][k] = e;
            s += e;
        }
        float inv = 1.0f / s;
#pragma unroll
        for (int k = 0; k < 16; k++) p[t][k] *= inv;
    }
    __syncthreads();
    if (t < 16) att_out[(size_t)n * KNB + t] = 0.5f * (p[0][t] + p[1][t]);
    for (int d = t; d < 256; d += 128) {
        int h = d >> 7;
        float acc = 0.f;
#pragma unroll
        for (int k = 0; k < 16; k++)
            acc = fmaf(p[h][k], KV[((size_t)n * KNB + k) * 512 + 256 + d], acc);
        ctx_out[(size_t)n * 256 + d] = acc;
    }
}

// ---------------- deterministic global sum of att ----------------
__global__ void red1_kernel(const float* __restrict__ att, float* __restrict__ part) {
    __shared__ float s[256];
    float a = 0.f;
    for (size_t i = (size_t)blockIdx.x * 256 + threadIdx.x; i < NE; i += (size_t)gridDim.x * 256)
        a += att[i];
    s[threadIdx.x] = a;
    __syncthreads();
    for (int o = 128; o; o >>= 1) {
        if (threadIdx.x < o) s[threadIdx.x] += s[threadIdx.x + o];
        __syncthreads();
    }
    if (threadIdx.x == 0) part[blockIdx.x] = s[0];
}

__global__ void red2_kernel(const float* __restrict__ part, float* __restrict__ sum) {
    __shared__ float s[512];
    int t = threadIdx.x;
    s[t] = (t < 320) ? part[t] : 0.f;
    __syncthreads();
    for (int o = 256; o; o >>= 1) {
        if (t < o) s[t] += s[t + o];
        __syncthreads();
    }
    if (t == 0) *sum = s[0];
}

// eid is int32 (JAX default x64-disabled: jnp.int64 request silently becomes int32)
__global__ void scatter_kernel(const float* __restrict__ att, const float* __restrict__ sum,
                               const int* __restrict__ eid, float* __restrict__ attn_map) {
    int i = blockIdx.x * blockDim.x + threadIdx.x;
    if (i < NE) {
        float v = att[i] / (*sum);
        int e = eid[i];
        if (e >= 0 && e < NE) attn_map[e] = v;
    }
}

// ---------------- launch ----------------
extern "C" void kernel_launch(void* const* d_in, const int* in_sizes, int n_in,
                              void* d_out, int out_size) {
    const float* node_emb   = (const float*)d_in[0];
    const float* dst_emb    = (const float*)d_in[1];
    const float* edge_feat  = (const float*)d_in[2];
    const float* timestamps = (const float*)d_in[3];
    const float* last_update= (const float*)d_in[4];
    const int*   src_idx    = (const int*)d_in[5];
    const int*   eid        = (const int*)d_in[6];
    const float* w_t = (const float*)d_in[7];
    const float* b_t = (const float*)d_in[8];
    const float* Wq = (const float*)d_in[9];
    const float* bq = (const float*)d_in[10];
    const float* Wk = (const float*)d_in[11];
    const float* bk = (const float*)d_in[12];
    const float* Wv = (const float*)d_in[13];
    const float* bv = (const float*)d_in[14];
    const float* Wo = (const float*)d_in[15];
    const float* bo = (const float*)d_in[16];
    const float* W1 = (const float*)d_in[17];
    const float* b1 = (const float*)d_in[18];
    const float* W2 = (const float*)d_in[19];
    const float* b2 = (const float*)d_in[20];

    float* out_h = (float*)d_out;
    float* attn_map = out_h + (size_t)N_DST * 128;

    float *pC, *pKV, *pNodeP, *pBkvN, *pBkvET, *pbkv, *pBq, *pBo, *pB1, *pB2;
    float *pquery, *pQ, *pctx, *pHb, *pX, *pH1, *patt, *ppart, *pattsum;
    cudaGetSymbolAddress((void**)&pC, g_C);
    cudaGetSymbolAddress((void**)&pKV, g_KV);
    cudaGetSymbolAddress((void**)&pNodeP, g_NodeP);
    cudaGetSymbolAddress((void**)&pBkvN, g_Bkv_node);
    cudaGetSymbolAddress((void**)&pBkvET, g_Bkv_et);
    cudaGetSymbolAddress((void**)&pbkv, g_bkv);
    cudaGetSymbolAddress((void**)&pBq, g_Bq);
    cudaGetSymbolAddress((void**)&pBo, g_Bo);
    cudaGetSymbolAddress((void**)&pB1, g_B1);
    cudaGetSymbolAddress((void**)&pB2, g_B2);
    cudaGetSymbolAddress((void**)&pquery, g_query);
    cudaGetSymbolAddress((void**)&pQ, g_Qm);
    cudaGetSymbolAddress((void**)&pctx, g_ctx);
    cudaGetSymbolAddress((void**)&pHb, g_Hb);
    cudaGetSymbolAddress((void**)&pX, g_X);
    cudaGetSymbolAddress((void**)&pH1, g_H1);
    cudaGetSymbolAddress((void**)&patt, g_att);
    cudaGetSymbolAddress((void**)&ppart, g_part);
    cudaGetSymbolAddress((void**)&pattsum, g_attsum);

    const int T = 256;
    // weight prep (tiny)
    build_Bkv_node_kernel<<<(128 * 512 + T - 1) / T, T>>>(Wk, Wv, bk, bv, pBkvN, pbkv);
    build_Bkv_et_kernel<<<(256 * 512 + T - 1) / T, T>>>(Wk, Wv, pBkvET);
    transpose_kernel<<<(256 * 256 + T - 1) / T, T>>>(Wq, pBq, 256, 256);
    transpose_kernel<<<(256 * 256 + T - 1) / T, T>>>(Wo, pBo, 256, 256);
    transpose_kernel<<<(128 * 384 + T - 1) / T, T>>>(W1, pB1, 128, 384);
    transpose_kernel<<<(128 * 128 + T - 1) / T, T>>>(W2, pB2, 128, 128);

    fill_attn_kernel<<<(NE + T - 1) / T, T>>>(attn_map);
    build_query_kernel<<<(N_DST * 256 + T - 1) / T, T>>>(dst_emb, b_t, pquery);
    {
        size_t tot = (size_t)NE * 256;
        build_C_kernel<<<(unsigned)((tot + T - 1) / T), T>>>(edge_feat, timestamps, last_update,
                                                             src_idx, w_t, b_t, pC);
    }

    // NodeP = node_emb @ Bkv_node + bkv   [100000, 512]
    {
        dim3 g(4, (N_SRC + 127) / 128);
        sgemm_kernel<<<g, 256>>>(node_emb, pBkvN, pbkv, pNodeP, N_SRC, 512, 128, 0, nullptr, nullptr);
    }
    // KV = C @ Bkv_et + NodeP[src]        [320000, 512]
    {
        dim3 g(4, (NE + 127) / 128);
        sgemm_kernel<<<g, 256>>>(pC, pBkvET, nullptr, pKV, NE, 512, 256, 0, pNodeP, src_idx);
    }
    // Q = query @ Bq + bq                 [20000, 256]
    {
        dim3 g(2, (N_DST + 127) / 128);
        sgemm_kernel<<<g, 256>>>(pquery, pBq, bq, pQ, N_DST, 256, 256, 0, nullptr, nullptr);
    }

    attn_kernel<<<N_DST, 128>>>(pQ, pKV, pctx, patt);
    red1_kernel<<<320, 256>>>(patt, ppart);
    red2_kernel<<<1, 512>>>(ppart, pattsum);

    // Hb = ctx @ Bo + bo                  [20000, 256]
    {
        dim3 g(2, (N_DST + 127) / 128);
        sgemm_kernel<<<g, 256>>>(pctx, pBo, bo, pHb, N_DST, 256, 256, 0, nullptr, nullptr);
    }
    build_X_kernel<<<(unsigned)(((size_t)N_DST * 384 + T - 1) / T), T>>>(dst_emb, pHb, pX);
    // H1 = relu(X @ B1 + b1)              [20000, 128]
    {
        dim3 g(1, (N_DST + 127) / 128);
        sgemm_kernel<<<g, 256>>>(pX, pB1, b1, pH1, N_DST, 128, 384, 1, nullptr, nullptr);
    }
    // out_h = H1 @ B2 + b2                [20000, 128]
    {
        dim3 g(1, (N_DST + 127) / 128);
        sgemm_kernel<<<g, 256>>>(pH1, pB2, b2, out_h, N_DST, 128, 128, 0, nullptr, nullptr);
    }

    scatter_kernel<<<(NE + T - 1) / T, T>>>(patt, pattsum, eid, attn_map);
}

// round 15
// speedup vs baseline: 1.1190x; 1.1190x over previous
#include <cuda_runtime.h>
#include <math.h>
#include <stdint.h>

#define N_DST 20000
#define N_SRC 100000
#define KNB 16
#define NE (N_DST * KNB)   // 320000 edges
#define D_NODE 128
#define D_TIME 128
#define D_EDGE 128
#define D_Q 256
#define D_K 384

// ---------------- static device scratch (no allocations allowed) ----------------
__device__ float g_C[(size_t)NE * 256];        // [edge_feat | te] per edge
__device__ float g_KV[(size_t)NE * 512];       // kproj(0:256) | vproj(256:512)
__device__ float g_NodeP[(size_t)N_SRC * 512]; // node_emb @ [Wk_node;Wv_node]^T + [bk;bv]
__device__ float g_Bkv_node[128 * 512];
__device__ float g_Bkv_et[256 * 512];
__device__ float g_bkv[512];
__device__ float g_Bq[256 * 256];
__device__ float g_Bo[256 * 256];
__device__ float g_B1[384 * 128];
__device__ float g_B2[128 * 128];
__device__ float g_query[(size_t)N_DST * 256];
__device__ float g_Qm[(size_t)N_DST * 256];
__device__ float g_ctx[(size_t)N_DST * 256];
__device__ float g_Hb[(size_t)N_DST * 256];
__device__ float g_X[(size_t)N_DST * 384];
__device__ float g_H1[(size_t)N_DST * 128];
__device__ float g_att[NE];
__device__ float g_part[320];
__device__ float g_attsum;

// ---------------- packed f32x2 helpers (Blackwell FFMA2) ----------------
__device__ __forceinline__ unsigned long long pack2_dup(float a) {
    unsigned long long r;
    asm("mov.b64 %0, {%1, %1};" : "=l"(r) : "f"(a));
    return r;
}
__device__ __forceinline__ void ffma2(unsigned long long& d, unsigned long long a,
                                      unsigned long long b) {
    asm("fma.rn.f32x2 %0, %1, %2, %3;" : "=l"(d) : "l"(a), "l"(b), "l"(d));
}

// ---------------- weight prep ----------------
__global__ void build_Bkv_node_kernel(const float* __restrict__ Wk, const float* __restrict__ Wv,
                                      const float* __restrict__ bk, const float* __restrict__ bv,
                                      float* __restrict__ B, float* __restrict__ bkv) {
    int idx = blockIdx.x * blockDim.x + threadIdx.x;
    if (idx < 128 * 512) {
        int j = idx >> 9, o = idx & 511;
        B[idx] = (o < 256) ? Wk[o * 384 + j] : Wv[(o - 256) * 384 + j];
    }
    if (idx < 512) bkv[idx] = (idx < 256) ? bk[idx] : bv[idx - 256];
}

__global__ void build_Bkv_et_kernel(const float* __restrict__ Wk, const float* __restrict__ Wv,
                                    float* __restrict__ B) {
    int idx = blockIdx.x * blockDim.x + threadIdx.x;
    if (idx < 256 * 512) {
        int j = idx >> 9, o = idx & 511;
        int col = 128 + j;
        B[idx] = (o < 256) ? Wk[o * 384 + col] : Wv[(o - 256) * 384 + col];
    }
}

// generic transpose: W is [O,I] (torch layout), out Bm is [I,O]
__global__ void transpose_kernel(const float* __restrict__ W, float* __restrict__ Bm,
                                 int O, int I) {
    int idx = blockIdx.x * blockDim.x + threadIdx.x;
    if (idx < O * I) {
        int j = idx / O, o = idx % O;
        Bm[idx] = W[o * I + j];
    }
}

// ---------------- elementwise builders ----------------
__global__ void fill_attn_kernel(float* __restrict__ attn_map) {
    int i = blockIdx.x * blockDim.x + threadIdx.x;
    if (i < NE) attn_map[i] = -1.0f;
}

__global__ void build_query_kernel(const float* __restrict__ dst_emb,
                                   const float* __restrict__ b_t,
                                   float* __restrict__ q) {
    int idx = blockIdx.x * blockDim.x + threadIdx.x;
    if (idx < N_DST * 256) {
        int n = idx >> 8, j = idx & 255;
        q[idx] = (j < 128) ? dst_emb[n * 128 + j] : cosf(b_t[j - 128]);
    }
}

__global__ void build_C_kernel(const float* __restrict__ edge_feat,
                               const float* __restrict__ timestamps,
                               const float* __restrict__ last_update,
                               const int* __restrict__ src_idx,
                               const float* __restrict__ w_t,
                               const float* __restrict__ b_t,
                               float* __restrict__ C) {
    size_t idx = (size_t)blockIdx.x * blockDim.x + threadIdx.x;
    if (idx < (size_t)NE * 256) {
        int e = (int)(idx >> 8);
        int j = (int)(idx & 255);
        float v;
        if (j < 128) {
            v = edge_feat[(size_t)e * 128 + j];
        } else {
            int j2 = j - 128;
            float dt = timestamps[e] - last_update[src_idx[e]];
            v = cosf(fmaf(dt, w_t[j2], b_t[j2]));
        }
        C[idx] = v;
    }
}

__global__ void build_X_kernel(const float* __restrict__ dst_emb,
                               const float* __restrict__ Hb,
                               float* __restrict__ X) {
    size_t idx = (size_t)blockIdx.x * blockDim.x + threadIdx.x;
    if (idx < (size_t)N_DST * 384) {
        int n = (int)(idx / 384);
        int j = (int)(idx % 384);
        X[idx] = (j < 128) ? dst_emb[n * 128 + j] : Hb[(size_t)n * 256 + (j - 128)];
    }
}

// ---------------- SGEMM: C[M,N] = A[M,K] @ B[K,N] (+bias)(+gather-add)(+relu) --------
// 128x128 block, BK=8, 256 threads, 8x8 per-thread tile, packed-f32x2 inner loop
__global__ __launch_bounds__(256) void sgemm_kernel(
    const float* __restrict__ A, const float* __restrict__ B,
    const float* __restrict__ bias, float* __restrict__ C,
    int M, int N, int K, int relu,
    const float* __restrict__ gtab, const int* __restrict__ gidx) {
    __shared__ float As[8][128];
    __shared__ float Bs[8][128];
    const int tid = threadIdx.x;
    const int brow = blockIdx.y * 128;
    const int bcol = blockIdx.x * 128;
    const int tx = tid & 15;
    const int ty = tid >> 4;
    // acc2[i][jp] packs columns (2*jp, 2*jp+1) of the 8-wide j tile
    unsigned long long acc2[8][4];
#pragma unroll
    for (int i = 0; i < 8; i++)
#pragma unroll
        for (int j = 0; j < 4; j++) acc2[i][j] = 0ull;

    const int a_row = tid >> 1;
    const int a_col = (tid & 1) * 4;
    const int b_row = tid >> 5;
    const int b_col = (tid & 31) * 4;
    const float* Ab = A + (size_t)brow * K;
    const float* Bb = B + bcol;
    const bool a_ok = (brow + a_row) < M;

    for (int k0 = 0; k0 < K; k0 += 8) {
        float4 av = make_float4(0.f, 0.f, 0.f, 0.f);
        if (a_ok) av = *reinterpret_cast<const float4*>(Ab + (size_t)a_row * K + k0 + a_col);
        float4 bv = *reinterpret_cast<const float4*>(Bb + (size_t)(k0 + b_row) * N + b_col);
        As[a_col + 0][a_row] = av.x;
        As[a_col + 1][a_row] = av.y;
        As[a_col + 2][a_row] = av.z;
        As[a_col + 3][a_row] = av.w;
        *reinterpret_cast<float4*>(&Bs[b_row][b_col]) = bv;
        __syncthreads();
#pragma unroll
        for (int kk = 0; kk < 8; kk++) {
            float4 a0 = *reinterpret_cast<const float4*>(&As[kk][ty * 4]);
            float4 a1 = *reinterpret_cast<const float4*>(&As[kk][64 + ty * 4]);
            float4 b0 = *reinterpret_cast<const float4*>(&Bs[kk][tx * 4]);
            float4 b1 = *reinterpret_cast<const float4*>(&Bs[kk][64 + tx * 4]);
            // b pairs are free: the float4 register quad is two aligned b64 pairs
            ulonglong2 bp0 = *reinterpret_cast<ulonglong2*>(&b0);
            ulonglong2 bp1 = *reinterpret_cast<ulonglong2*>(&b1);
            float af[8] = {a0.x, a0.y, a0.z, a0.w, a1.x, a1.y, a1.z, a1.w};
#pragma unroll
            for (int i = 0; i < 8; i++) {
                unsigned long long aa = pack2_dup(af[i]);
                ffma2(acc2[i][0], aa, bp0.x);
                ffma2(acc2[i][1], aa, bp0.y);
                ffma2(acc2[i][2], aa, bp1.x);
                ffma2(acc2[i][3], aa, bp1.y);
            }
        }
        __syncthreads();
    }
#pragma unroll
    for (int i = 0; i < 8; i++) {
        int r = brow + ((i < 4) ? (ty * 4 + i) : (64 + ty * 4 + i - 4));
        if (r >= M) continue;
        const float* grow = gtab ? (gtab + (size_t)gidx[r] * N) : nullptr;
#pragma unroll
        for (int jj = 0; jj < 2; jj++) {
            int c = bcol + ((jj == 0) ? tx * 4 : 64 + tx * 4);
            float2 p0 = *reinterpret_cast<float2*>(&acc2[i][jj * 2 + 0]);
            float2 p1 = *reinterpret_cast<float2*>(&acc2[i][jj * 2 + 1]);
            float4 v = make_float4(p0.x, p0.y, p1.x, p1.y);
            if (bias) {
                v.x += bias[c]; v.y += bias[c + 1]; v.z += bias[c + 2]; v.w += bias[c + 3];
            }
            if (grow) {
                float4 g = *reinterpret_cast<const float4*>(grow + c);
                v.x += g.x; v.y += g.y; v.z += g.z; v.w += g.w;
            }
            if (relu) {
                v.x = fmaxf(v.x, 0.f); v.y = fmaxf(v.y, 0.f);
                v.z = fmaxf(v.z, 0.f); v.w = fmaxf(v.w, 0.f);
            }
            *reinterpret_cast<float4*>(C + (size_t)r * N + c) = v;
        }
    }
}

// ---------------- attention: one block (128 thr) per destination node ----------------
__global__ void attn_kernel(const float* __restrict__ Q, const float* __restrict__ KV,
                            float* __restrict__ ctx_out, float* __restrict__ att_out) {
    int n = blockIdx.x;
    int t = threadIdx.x;  // 0..127
    __shared__ float q[256];
    __shared__ float sc[2][16];
    __shared__ float p[2][16];
    const float scale = 0.08838834764831845f;  // 1/sqrt(128)
    q[t] = Q[(size_t)n * 256 + t] * scale;
    q[t + 128] = Q[(size_t)n * 256 + 128 + t] * scale;
    __syncthreads();
    int warp = t >> 5, lane = t & 31;
    for (int pair = warp; pair < 32; pair += 4) {
        int h = pair >> 4, k = pair & 15;
        const float* kr = KV + ((size_t)n * KNB + k) * 512 + h * 128;
        float s = 0.f;
#pragma unroll
        for (int j = 0; j < 4; j++) s = fmaf(q[h * 128 + lane + 32 * j], kr[lane + 32 * j], s);
#pragma unroll
        for (int off = 16; off; off >>= 1) s += __shfl_xor_sync(0xffffffffu, s, off);
        if (lane == 0) sc[h][k] = s;
    }
    __syncthreads();
    if (t < 2) {
        float m = -1e30f;
#pragma unroll
        for (int k = 0; k < 16; k++) m = fmaxf(m, sc[t][k]);
        float s = 0.f;
#pragma unroll
        for (int k = 0; k < 16; k++) {
            float e = expf(sc[t][k] - m);
            p[t][k] = e;
            s += e;
        }
        float inv = 1.0f / s;
#pragma unroll
        for (int k = 0; k < 16; k++) p[t][k] *= inv;
    }
    __syncthreads();
    if (t < 16) att_out[(size_t)n * KNB + t] = 0.5f * (p[0][t] + p[1][t]);
    for (int d = t; d < 256; d += 128) {
        int h = d >> 7;
        float acc = 0.f;
#pragma unroll
        for (int k = 0; k < 16; k++)
            acc = fmaf(p[h][k], KV[((size_t)n * KNB + k) * 512 + 256 + d], acc);
        ctx_out[(size_t)n * 256 + d] = acc;
    }
}

// ---------------- deterministic global sum of att ----------------
__global__ void red1_kernel(const float* __restrict__ att, float* __restrict__ part) {
    __shared__ float s[256];
    float a = 0.f;
    for (size_t i = (size_t)blockIdx.x * 256 + threadIdx.x; i < NE; i += (size_t)gridDim.x * 256)
        a += att[i];
    s[threadIdx.x] = a;
    __syncthreads();
    for (int o = 128; o; o >>= 1) {
        if (threadIdx.x < o) s[threadIdx.x] += s[threadIdx.x + o];
        __syncthreads();
    }
    if (threadIdx.x == 0) part[blockIdx.x] = s[0];
}

__global__ void red2_kernel(const float* __restrict__ part, float* __restrict__ sum) {
    __shared__ float s[512];
    int t = threadIdx.x;
    s[t] = (t < 320) ? part[t] : 0.f;
    __syncthreads();
    for (int o = 256; o; o >>= 1) {
        if (t < o) s[t] += s[t + o];
        __syncthreads();
    }
    if (t == 0) *sum = s[0];
}

// eid is int32 (JAX default x64-disabled: jnp.int64 request silently becomes int32)
__global__ void scatter_kernel(const float* __restrict__ att, const float* __restrict__ sum,
                               const int* __restrict__ eid, float* __restrict__ attn_map) {
    int i = blockIdx.x * blockDim.x + threadIdx.x;
    if (i < NE) {
        float v = att[i] / (*sum);
        int e = eid[i];
        if (e >= 0 && e < NE) attn_map[e] = v;
    }
}

// ---------------- launch ----------------
extern "C" void kernel_launch(void* const* d_in, const int* in_sizes, int n_in,
                              void* d_out, int out_size) {
    const float* node_emb   = (const float*)d_in[0];
    const float* dst_emb    = (const float*)d_in[1];
    const float* edge_feat  = (const float*)d_in[2];
    const float* timestamps = (const float*)d_in[3];
    const float* last_update= (const float*)d_in[4];
    const int*   src_idx    = (const int*)d_in[5];
    const int*   eid        = (const int*)d_in[6];
    const float* w_t = (const float*)d_in[7];
    const float* b_t = (const float*)d_in[8];
    const float* Wq = (const float*)d_in[9];
    const float* bq = (const float*)d_in[10];
    const float* Wk = (const float*)d_in[11];
    const float* bk = (const float*)d_in[12];
    const float* Wv = (const float*)d_in[13];
    const float* bv = (const float*)d_in[14];
    const float* Wo = (const float*)d_in[15];
    const float* bo = (const float*)d_in[16];
    const float* W1 = (const float*)d_in[17];
    const float* b1 = (const float*)d_in[18];
    const float* W2 = (const float*)d_in[19];
    const float* b2 = (const float*)d_in[20];

    float* out_h = (float*)d_out;
    float* attn_map = out_h + (size_t)N_DST * 128;

    float *pC, *pKV, *pNodeP, *pBkvN, *pBkvET, *pbkv, *pBq, *pBo, *pB1, *pB2;
    float *pquery, *pQ, *pctx, *pHb, *pX, *pH1, *patt, *ppart, *pattsum;
    cudaGetSymbolAddress((void**)&pC, g_C);
    cudaGetSymbolAddress((void**)&pKV, g_KV);
    cudaGetSymbolAddress((void**)&pNodeP, g_NodeP);
    cudaGetSymbolAddress((void**)&pBkvN, g_Bkv_node);
    cudaGetSymbolAddress((void**)&pBkvET, g_Bkv_et);
    cudaGetSymbolAddress((void**)&pbkv, g_bkv);
    cudaGetSymbolAddress((void**)&pBq, g_Bq);
    cudaGetSymbolAddress((void**)&pBo, g_Bo);
    cudaGetSymbolAddress((void**)&pB1, g_B1);
    cudaGetSymbolAddress((void**)&pB2, g_B2);
    cudaGetSymbolAddress((void**)&pquery, g_query);
    cudaGetSymbolAddress((void**)&pQ, g_Qm);
    cudaGetSymbolAddress((void**)&pctx, g_ctx);
    cudaGetSymbolAddress((void**)&pHb, g_Hb);
    cudaGetSymbolAddress((void**)&pX, g_X);
    cudaGetSymbolAddress((void**)&pH1, g_H1);
    cudaGetSymbolAddress((void**)&patt, g_att);
    cudaGetSymbolAddress((void**)&ppart, g_part);
    cudaGetSymbolAddress((void**)&pattsum, g_attsum);

    const int T = 256;
    // weight prep (tiny)
    build_Bkv_node_kernel<<<(128 * 512 + T - 1) / T, T>>>(Wk, Wv, bk, bv, pBkvN, pbkv);
    build_Bkv_et_kernel<<<(256 * 512 + T - 1) / T, T>>>(Wk, Wv, pBkvET);
    transpose_kernel<<<(256 * 256 + T - 1) / T, T>>>(Wq, pBq, 256, 256);
    transpose_kernel<<<(256 * 256 + T - 1) / T, T>>>(Wo, pBo, 256, 256);
    transpose_kernel<<<(128 * 384 + T - 1) / T, T>>>(W1, pB1, 128, 384);
    transpose_kernel<<<(128 * 128 + T - 1) / T, T>>>(W2, pB2, 128, 128);

    fill_attn_kernel<<<(NE + T - 1) / T, T>>>(attn_map);
    build_query_kernel<<<(N_DST * 256 + T - 1) / T, T>>>(dst_emb, b_t, pquery);
    {
        size_t tot = (size_t)NE * 256;
        build_C_kernel<<<(unsigned)((tot + T - 1) / T), T>>>(edge_feat, timestamps, last_update,
                                                             src_idx, w_t, b_t, pC);
    }

    // NodeP = node_emb @ Bkv_node + bkv   [100000, 512]
    {
        dim3 g(4, (N_SRC + 127) / 128);
        sgemm_kernel<<<g, 256>>>(node_emb, pBkvN, pbkv, pNodeP, N_SRC, 512, 128, 0, nullptr, nullptr);
    }
    // KV = C @ Bkv_et + NodeP[src]        [320000, 512]
    {
        dim3 g(4, (NE + 127) / 128);
        sgemm_kernel<<<g, 256>>>(pC, pBkvET, nullptr, pKV, NE, 512, 256, 0, pNodeP, src_idx);
    }
    // Q = query @ Bq + bq                 [20000, 256]
    {
        dim3 g(2, (N_DST + 127) / 128);
        sgemm_kernel<<<g, 256>>>(pquery, pBq, bq, pQ, N_DST, 256, 256, 0, nullptr, nullptr);
    }

    attn_kernel<<<N_DST, 128>>>(pQ, pKV, pctx, patt);
    red1_kernel<<<320, 256>>>(patt, ppart);
    red2_kernel<<<1, 512>>>(ppart, pattsum);

    // Hb = ctx @ Bo + bo                  [20000, 256]
    {
        dim3 g(2, (N_DST + 127) / 128);
        sgemm_kernel<<<g, 256>>>(pctx, pBo, bo, pHb, N_DST, 256, 256, 0, nullptr, nullptr);
    }
    build_X_kernel<<<(unsigned)(((size_t)N_DST * 384 + T - 1) / T), T>>>(dst_emb, pHb, pX);
    // H1 = relu(X @ B1 + b1)              [20000, 128]
    {
        dim3 g(1, (N_DST + 127) / 128);
        sgemm_kernel<<<g, 256>>>(pX, pB1, b1, pH1, N_DST, 128, 384, 1, nullptr, nullptr);
    }
    // out_h = H1 @ B2 + b2                [20000, 128]
    {
        dim3 g(1, (N_DST + 127) / 128);
        sgemm_kernel<<<g, 256>>>(pH1, pB2, b2, out_h, N_DST, 128, 128, 0, nullptr, nullptr);
    }

    scatter_kernel<<<(NE + T - 1) / T, T>>>(patt, pattsum, eid, attn_map);
}